// round 5
// baseline (speedup 1.0000x reference)
#include <cuda_runtime.h>

// ---------------------------------------------------------------------------
// RNN_32109175505717: 3-layer tanh RNN (B=4096, T=128, HID=64, F=14) + FC head
// R5 (= R4 retry; container infra flake, kernel never ran):
// scalar fp32 fma.rn.f32x2 path (tcgen05 unavailable: harness targets sm_103
// without the 'a' feature set). Same smem layout as the passing R2 kernel,
// but 512 threads/CTA -> 16 warps/SM (4/SMSP) to halve latency exposure that
// ncu showed (issue=25.8%, occ=12.5%).
// Thread tile: 2 j outputs x 1 e-pair (2 batch elems).
// ---------------------------------------------------------------------------

#define HID        64
#define F_IN       14
#define T_STEPS    128
#define B_TOTAL    4096
#define ELEMS_BLK  32
#define NTHREADS   512
#define NBLOCKS    (B_TOTAL / ELEMS_BLK)   // 128

typedef unsigned long long ull;

// ---- shared memory layout (units: ull = 8 bytes = one f32x2) --------------
#define OFF_WIH0   0                      // 14*64
#define OFF_WHH0   (OFF_WIH0 + 14*64)     // 64*64
#define OFF_WIH1   (OFF_WHH0 + 64*64)
#define OFF_WHH1   (OFF_WIH1 + 64*64)
#define OFF_WIH2   (OFF_WHH1 + 64*64)
#define OFF_WHH2   (OFF_WIH2 + 64*64)
#define OFF_H      (OFF_WHH2 + 64*64)     // 3 layers * 2 bufs * 64k * 16 pairs
#define OFF_XS     (OFF_H + 3*2*64*16)    // 14 * 16 pairs
#define OFF_RED    (OFF_XS + 14*16)       // 256 floats = 128 ull
#define SMEM_ULL   (OFF_RED + 128)
#define SMEM_BYTES (SMEM_ULL * 8)         // 222976 bytes

// ---- f32x2 helpers --------------------------------------------------------
__device__ __forceinline__ ull pack2(float lo, float hi) {
    ull r; asm("mov.b64 %0, {%1, %2};" : "=l"(r) : "f"(lo), "f"(hi)); return r;
}
__device__ __forceinline__ void unpack2(ull v, float& lo, float& hi) {
    asm("mov.b64 {%0, %1}, %2;" : "=f"(lo), "=f"(hi) : "l"(v));
}
__device__ __forceinline__ ull fma2(ull a, ull b, ull c) {
    ull d; asm("fma.rn.f32x2 %0, %1, %2, %3;" : "=l"(d) : "l"(a), "l"(b), "l"(c));
    return d;
}

__device__ __forceinline__ float fast_tanh(float x) {
    x = fminf(fmaxf(x, -12.0f), 12.0f);     // avoid inf/inf
    float e = __expf(x + x);
    return __fdividef(e - 1.0f, e + 1.0f);
}
__device__ __forceinline__ ull tanh2(ull v) {
    float a, b; unpack2(v, a, b);
    return pack2(fast_tanh(a), fast_tanh(b));
}

// ---- core matvec accumulate ----------------------------------------------
// hsrc: packed e-pairs, stride 16 ull per k.  wsrc: dup pairs {w,w},
// stride 64 ull per k.  Thread accumulates 2 j outputs for one e-pair.
template<int NK>
__device__ __forceinline__ void mv2(const ull* __restrict__ hsrc,
                                    const ull* __restrict__ wsrc,
                                    int et, int jt2, ull& a0, ull& a1)
{
#pragma unroll 16
    for (int k = 0; k < NK; ++k) {
        ull hv = hsrc[k * 16 + et];                                       // LDS.64
        ulonglong2 wv = *reinterpret_cast<const ulonglong2*>(wsrc + k * 64 + jt2); // LDS.128
        a0 = fma2(hv, wv.x, a0);   // {e0,e1} x j0
        a1 = fma2(hv, wv.y, a1);   // {e0,e1} x j1
    }
}

// ---- weight loader: g[j][k] row-major -> smem dup-transposed s[k*64 + j] --
__device__ __forceinline__ void load_wdup(const float* __restrict__ g, ull* s,
                                          int cols /*k-count*/)
{
    int total = HID * cols;
    for (int idx = threadIdx.x; idx < total; idx += NTHREADS) {
        int j = idx / cols;
        int k = idx - j * cols;
        float w = g[idx];
        s[k * HID + j] = pack2(w, w);
    }
}

__global__ void __launch_bounds__(NTHREADS, 1)
rnn_fused_kernel(const float* __restrict__ x,
                 const float* __restrict__ Wih0, const float* __restrict__ Whh0,
                 const float* __restrict__ bih0, const float* __restrict__ bhh0,
                 const float* __restrict__ Wih1, const float* __restrict__ Whh1,
                 const float* __restrict__ bih1, const float* __restrict__ bhh1,
                 const float* __restrict__ Wih2, const float* __restrict__ Whh2,
                 const float* __restrict__ bih2, const float* __restrict__ bhh2,
                 const float* __restrict__ fc1w, const float* __restrict__ fc1b,
                 const float* __restrict__ fc2w, const float* __restrict__ fc2b,
                 float* __restrict__ out)
{
    extern __shared__ ull sm[];

    // ---- stage weights into shared memory (duplicated pairs) ----
    load_wdup(Wih0, sm + OFF_WIH0, F_IN);
    load_wdup(Whh0, sm + OFF_WHH0, HID);
    load_wdup(Wih1, sm + OFF_WIH1, HID);
    load_wdup(Whh1, sm + OFF_WHH1, HID);
    load_wdup(Wih2, sm + OFF_WIH2, HID);
    load_wdup(Whh2, sm + OFF_WHH2, HID);

    // zero hidden-state buffers (both parity buffers, all 3 layers)
    for (int idx = threadIdx.x; idx < 3 * 2 * 64 * 16; idx += NTHREADS)
        sm[OFF_H + idx] = 0ull;

    const int tid = threadIdx.x;
    const int et  = tid & 15;       // e-pair index: elems {2et, 2et+1}
    const int jt  = tid >> 4;       // j-tile: outputs {2jt, 2jt+1}
    const int jt2 = jt * 2;
    const int j0  = jt2, j1 = jt2 + 1;

    // per-thread duplicated biases (b_ih + b_hh always add together)
    const ull b0j0 = pack2(bih0[j0] + bhh0[j0], bih0[j0] + bhh0[j0]);
    const ull b0j1 = pack2(bih0[j1] + bhh0[j1], bih0[j1] + bhh0[j1]);
    const ull b1j0 = pack2(bih1[j0] + bhh1[j0], bih1[j0] + bhh1[j0]);
    const ull b1j1 = pack2(bih1[j1] + bhh1[j1], bih1[j1] + bhh1[j1]);
    const ull b2j0 = pack2(bih2[j0] + bhh2[j0], bih2[j0] + bhh2[j0]);
    const ull b2j1 = pack2(bih2[j1] + bhh2[j1], bih2[j1] + bhh2[j1]);

    const float* xblk = x + (size_t)blockIdx.x * ELEMS_BLK * T_STEPS * F_IN;
    float* xs_f = (float*)(sm + OFF_XS);    // xs[f][32 elems] fp32 view

    __syncthreads();

    for (int t = 0; t < T_STEPS; ++t) {
        const int Wb = t & 1;
        const int Rb = Wb ^ 1;
        ull* h0R = sm + OFF_H + (0 * 2 + Rb) * 1024;
        ull* h0W = sm + OFF_H + (0 * 2 + Wb) * 1024;
        ull* h1R = sm + OFF_H + (1 * 2 + Rb) * 1024;
        ull* h1W = sm + OFF_H + (1 * 2 + Wb) * 1024;
        ull* h2R = sm + OFF_H + (2 * 2 + Rb) * 1024;
        ull* h2W = sm + OFF_H + (2 * 2 + Wb) * 1024;

        // stage x[:, t, :]: one scalar per thread (448 <= 512)
        if (tid < ELEMS_BLK * F_IN) {
            int e = tid / F_IN;
            int f = tid - e * F_IN;
            xs_f[f * ELEMS_BLK + e] = xblk[e * (T_STEPS * F_IN) + t * F_IN + f];
        }
        __syncthreads();

        // ---- layer 0 ----
        {
            ull a0 = b0j0, a1 = b0j1;
            mv2<F_IN>(sm + OFF_XS, sm + OFF_WIH0, et, jt2, a0, a1);
            mv2<HID >(h0R,         sm + OFF_WHH0, et, jt2, a0, a1);
            h0W[j0 * 16 + et] = tanh2(a0);
            h0W[j1 * 16 + et] = tanh2(a1);
        }
        __syncthreads();

        // ---- layer 1 ----
        {
            ull a0 = b1j0, a1 = b1j1;
            mv2<HID>(h0W, sm + OFF_WIH1, et, jt2, a0, a1);
            mv2<HID>(h1R, sm + OFF_WHH1, et, jt2, a0, a1);
            h1W[j0 * 16 + et] = tanh2(a0);
            h1W[j1 * 16 + et] = tanh2(a1);
        }
        __syncthreads();

        // ---- layer 2 ----
        {
            ull a0 = b2j0, a1 = b2j1;
            mv2<HID>(h1W, sm + OFF_WIH2, et, jt2, a0, a1);
            mv2<HID>(h2R, sm + OFF_WHH2, et, jt2, a0, a1);
            h2W[j0 * 16 + et] = tanh2(a0);
            h2W[j1 * 16 + et] = tanh2(a1);
        }
        // no barrier needed here: next-iteration barrier (after x staging)
        // separates these stores from their consumers (layer 2 of t+1),
        // and xs writers are separated from layer-0 readers by the
        // layer-0 barrier of step t.
    }
    __syncthreads();

    // ---- FC head on final h2 (t=127 wrote parity buffer 1) ----
    const float* h2f = (const float*)(sm + OFF_H + (2 * 2 + 1) * 1024); // [k][32]
    if (tid < 256) {
        int e  = tid >> 3;         // 0..31  element within block
        int mg = tid & 7;          // 0..7   group of 4 fc1 units
        float contrib = 0.0f;
#pragma unroll
        for (int mi = 0; mi < 4; ++mi) {
            int m = mg * 4 + mi;
            float s = fc1b[m];
#pragma unroll 16
            for (int k = 0; k < HID; ++k)
                s = fmaf(fc1w[m * HID + k], h2f[k * 32 + e], s);
            contrib = fmaf(fc2w[m], fmaxf(s, 0.0f), contrib);
        }
        float* red = (float*)(sm + OFF_RED);
        red[tid] = contrib;        // red[e*8 + mg]
    }
    __syncthreads();
    if (tid < ELEMS_BLK) {
        float* red = (float*)(sm + OFF_RED);
        float s = fc2b[0];
#pragma unroll
        for (int i = 0; i < 8; ++i) s += red[tid * 8 + i];
        out[blockIdx.x * ELEMS_BLK + tid] = s;
    }
}

extern "C" void kernel_launch(void* const* d_in, const int* in_sizes, int n_in,
                              void* d_out, int out_size)
{
    const float* x    = (const float*)d_in[0];
    const float* Wih0 = (const float*)d_in[1];
    const float* Whh0 = (const float*)d_in[2];
    const float* bih0 = (const float*)d_in[3];
    const float* bhh0 = (const float*)d_in[4];
    const float* Wih1 = (const float*)d_in[5];
    const float* Whh1 = (const float*)d_in[6];
    const float* bih1 = (const float*)d_in[7];
    const float* bhh1 = (const float*)d_in[8];
    const float* Wih2 = (const float*)d_in[9];
    const float* Whh2 = (const float*)d_in[10];
    const float* bih2 = (const float*)d_in[11];
    const float* bhh2 = (const float*)d_in[12];
    const float* fc1w = (const float*)d_in[13];
    const float* fc1b = (const float*)d_in[14];
    const float* fc2w = (const float*)d_in[15];
    const float* fc2b = (const float*)d_in[16];
    float* out = (float*)d_out;

    cudaFuncSetAttribute(rnn_fused_kernel,
                         cudaFuncAttributeMaxDynamicSharedMemorySize, SMEM_BYTES);

    rnn_fused_kernel<<<NBLOCKS, NTHREADS, SMEM_BYTES>>>(
        x, Wih0, Whh0, bih0, bhh0,
        Wih1, Whh1, bih1, bhh1,
        Wih2, Whh2, bih2, bhh2,
        fc1w, fc1b, fc2w, fc2b, out);
}

// round 6
// speedup vs baseline: 1.5597x; 1.5597x over previous
#include <cuda_runtime.h>

// ---------------------------------------------------------------------------
// RNN_32109175505717: 3-layer tanh RNN (B=4096, T=128, HID=64, F=14) + FC head
// R6: L1-throughput-targeted redesign. ncu showed L1=73-79% (bound), fma ~20-25%.
// Thread tile 4j x 8e with k-split 4 (16-k partials + smem reduction):
// requests 1.5 B/MAC vs 4 B/MAC previously. Weights stored fp32 non-dup,
// {w,w} pairs packed on the fly (ALU pipe). 256 threads, 128 blocks.
// ---------------------------------------------------------------------------

#define HID        64
#define F_IN       14
#define T_STEPS    128
#define B_TOTAL    4096
#define ELEMS_BLK  32
#define NTHREADS   256
#define NBLOCKS    (B_TOTAL / ELEMS_BLK)   // 128

typedef unsigned long long ull;

// ---- smem layout ----------------------------------------------------------
// float region (weights, transposed to [k][j]):
#define WF_HH0   0
#define WF_IH1   (WF_HH0 + 64*64)
#define WF_HH1   (WF_IH1 + 64*64)
#define WF_IH2   (WF_HH1 + 64*64)
#define WF_HH2   (WF_IH2 + 64*64)
#define WF_IH0   (WF_HH2 + 64*64)          // 14*64
#define WF_END   (WF_IH0 + 14*64)          // 21376 floats
// ull region (starts right after, 16B aligned):
#define U_BASE   ((WF_END + 3) / 4 * 2)    // ull index; WF_END f32 -> ull
#define U_H0     (U_BASE)                  // 64k x 16 e-pairs
#define U_H1     (U_H0 + 1024)
#define U_H2     (U_H1 + 1024)
#define U_XS     (U_H2 + 1024)             // 14f x 16 e-pairs
#define U_RED    (U_XS + 224)              // red[i<16][tid<256] : 4096 ull
#define U_BIAS   (U_RED + 4096)            // 3*64 f32 = 96 ull
#define U_FCRED  (U_BIAS + 96)             // 256 f32 = 128 ull
#define SMEM_ULL (U_FCRED + 128)
#define SMEM_BYTES (SMEM_ULL * 8)          // ~150 KB

// ---- f32x2 helpers --------------------------------------------------------
__device__ __forceinline__ ull pack2(float lo, float hi) {
    ull r; asm("mov.b64 %0, {%1, %2};" : "=l"(r) : "f"(lo), "f"(hi)); return r;
}
__device__ __forceinline__ void unpack2(ull v, float& lo, float& hi) {
    asm("mov.b64 {%0, %1}, %2;" : "=f"(lo), "=f"(hi) : "l"(v));
}
__device__ __forceinline__ ull fma2(ull a, ull b, ull c) {
    ull d; asm("fma.rn.f32x2 %0, %1, %2, %3;" : "=l"(d) : "l"(a), "l"(b), "l"(c));
    return d;
}
__device__ __forceinline__ ull add2(ull a, ull b) {
    ull d; asm("add.rn.f32x2 %0, %1, %2;" : "=l"(d) : "l"(a), "l"(b));
    return d;
}
__device__ __forceinline__ float fast_tanh(float x) {
    x = fminf(fmaxf(x, -12.0f), 12.0f);
    float e = __expf(x + x);
    return __fdividef(e - 1.0f, e + 1.0f);
}
__device__ __forceinline__ ull tanh2(ull v) {
    float a, b; unpack2(v, a, b);
    return pack2(fast_tanh(a), fast_tanh(b));
}

// ---- matvec partial: NK k-steps starting at koff ---------------------------
// wf: [k][64j] f32.  hsrc: [k][16 e-pairs] ull.  acc a[j 0..3][ep 0..3].
__device__ __forceinline__ void mv_part(const float* __restrict__ wf,
                                        const ull* __restrict__ hsrc,
                                        int koff, int nk, int jq4, int ep0,
                                        ull a[4][4])
{
#pragma unroll 16
    for (int k = 0; k < nk; ++k) {
        const ull* hr = hsrc + (koff + k) * 16 + ep0;
        ulonglong2 h01 = *reinterpret_cast<const ulonglong2*>(hr);
        ulonglong2 h23 = *reinterpret_cast<const ulonglong2*>(hr + 2);
        float4 wv = *reinterpret_cast<const float4*>(wf + (koff + k) * 64 + jq4);
        ull pw0 = pack2(wv.x, wv.x), pw1 = pack2(wv.y, wv.y);
        ull pw2 = pack2(wv.z, wv.z), pw3 = pack2(wv.w, wv.w);
        a[0][0] = fma2(h01.x, pw0, a[0][0]); a[0][1] = fma2(h01.y, pw0, a[0][1]);
        a[0][2] = fma2(h23.x, pw0, a[0][2]); a[0][3] = fma2(h23.y, pw0, a[0][3]);
        a[1][0] = fma2(h01.x, pw1, a[1][0]); a[1][1] = fma2(h01.y, pw1, a[1][1]);
        a[1][2] = fma2(h23.x, pw1, a[1][2]); a[1][3] = fma2(h23.y, pw1, a[1][3]);
        a[2][0] = fma2(h01.x, pw2, a[2][0]); a[2][1] = fma2(h01.y, pw2, a[2][1]);
        a[2][2] = fma2(h23.x, pw2, a[2][2]); a[2][3] = fma2(h23.y, pw2, a[2][3]);
        a[3][0] = fma2(h01.x, pw3, a[3][0]); a[3][1] = fma2(h01.y, pw3, a[3][1]);
        a[3][2] = fma2(h23.x, pw3, a[3][2]); a[3][3] = fma2(h23.y, pw3, a[3][3]);
    }
}

// store partials to red[i][tid], i = j*4+ep
__device__ __forceinline__ void sts_partials(ull* red, int tid, ull a[4][4]) {
#pragma unroll
    for (int jj = 0; jj < 4; ++jj)
#pragma unroll
        for (int pp = 0; pp < 4; ++pp)
            red[(jj * 4 + pp) * 256 + tid] = a[jj][pp];
}

// out-phase: reduce 4 kc partials, +bias, tanh, write h
__device__ __forceinline__ void out_phase(const ull* red, ull* hdst,
                                          const float* bias, int tid)
{
    int oj = tid >> 2;          // 0..63
    int ov = tid & 3;           // ep group: ep = ov*4+el
    // producer thread id (kc varies): jq = oj>>2 ; w = jq>>1 ; jql = jq&1 ; u = ov
    int pbase = ((oj >> 3) << 5) | (((oj >> 2) & 1) << 2) | ov;
    float bj = bias[oj];
    ull bpack = pack2(bj, bj);
    ull res[4];
#pragma unroll
    for (int el = 0; el < 4; ++el) {
        int i = (oj & 3) * 4 + el;
        const ull* rp = red + i * 256 + pbase;
        ull s01 = add2(rp[0], rp[8]);
        ull s23 = add2(rp[16], rp[24]);
        res[el] = tanh2(add2(add2(s01, s23), bpack));
    }
    ull* hp = hdst + oj * 16 + ov * 4;
    *reinterpret_cast<ulonglong2*>(hp)     = make_ulonglong2(res[0], res[1]);
    *reinterpret_cast<ulonglong2*>(hp + 2) = make_ulonglong2(res[2], res[3]);
}

__global__ void __launch_bounds__(NTHREADS, 1)
rnn_fused_kernel(const float* __restrict__ x,
                 const float* __restrict__ Wih0, const float* __restrict__ Whh0,
                 const float* __restrict__ bih0, const float* __restrict__ bhh0,
                 const float* __restrict__ Wih1, const float* __restrict__ Whh1,
                 const float* __restrict__ bih1, const float* __restrict__ bhh1,
                 const float* __restrict__ Wih2, const float* __restrict__ Whh2,
                 const float* __restrict__ bih2, const float* __restrict__ bhh2,
                 const float* __restrict__ fc1w, const float* __restrict__ fc1b,
                 const float* __restrict__ fc2w, const float* __restrict__ fc2b,
                 float* __restrict__ out)
{
    extern __shared__ ull smu[];
    float* smf = (float*)smu;
    const int tid = threadIdx.x;

    // ---- stage weights transposed [k][j], fp32 non-dup ----
    {
        // 64x64 matrices
        const float* gsrc[5] = { Whh0, Wih1, Whh1, Wih2, Whh2 };
        const int    goff[5] = { WF_HH0, WF_IH1, WF_HH1, WF_IH2, WF_HH2 };
#pragma unroll
        for (int m = 0; m < 5; ++m) {
            const float* g = gsrc[m];
            float* s = smf + goff[m];
            for (int idx = tid; idx < 64 * 64; idx += NTHREADS) {
                int j = idx >> 6, k = idx & 63;     // g[j][k]
                s[k * 64 + j] = g[idx];
            }
        }
        // Wih0 [64j][14f] -> [f][64j]
        for (int idx = tid; idx < 64 * F_IN; idx += NTHREADS) {
            int j = idx / F_IN, f = idx - j * F_IN;
            smf[WF_IH0 + f * 64 + j] = Wih0[idx];
        }
    }
    // zero h buffers
    for (int i = tid; i < 3 * 1024; i += NTHREADS) smu[U_H0 + i] = 0ull;
    // biases
    float* bias_s = (float*)(smu + U_BIAS);
    if (tid < 64)       bias_s[tid]       = bih0[tid] + bhh0[tid];
    else if (tid < 128) bias_s[tid]       = bih1[tid - 64] + bhh1[tid - 64];
    else if (tid < 192) bias_s[tid]       = bih2[tid - 128] + bhh2[tid - 128];

    // ---- thread mapping ----
    const int w    = tid >> 5;
    const int lane = tid & 31;
    const int kc   = lane >> 3;          // 0..3 (phase-uniform: no k-row conflicts)
    const int jql  = (lane >> 2) & 1;
    const int u    = lane & 3;
    const int jq   = w * 2 + jql;        // 0..15
    const int jq4  = jq * 4;
    const int ep0  = u * 4;
    const int k0   = kc * 16;
    const int f0   = kc * 4;
    const int fn   = (F_IN - f0) < 4 ? (F_IN - f0) : 4;   // kc3: 2

    const float* xblk = x + (size_t)blockIdx.x * ELEMS_BLK * T_STEPS * F_IN;
    float* xs_f = (float*)(smu + U_XS);       // [f][32e] floats == [f][16ep] ull
    ull* red    = smu + U_RED;
    ull* H0 = smu + U_H0; ull* H1 = smu + U_H1; ull* H2 = smu + U_H2;

    // stage x(t=0): 448 scalars, 2 per thread
    for (int idx = tid; idx < ELEMS_BLK * F_IN; idx += NTHREADS) {
        int e = idx / F_IN, f = idx - e * F_IN;
        xs_f[f * ELEMS_BLK + e] = xblk[e * (T_STEPS * F_IN) + f];
    }
    __syncthreads();

    for (int t = 0; t < T_STEPS; ++t) {
        // ---- layer 0: Wih0*x share + Whh0*h0 partial ----
        {
            ull a[4][4] = {};
            mv_part(smf + WF_IH0, smu + U_XS, f0, fn, jq4, ep0, a);
            mv_part(smf + WF_HH0, H0, k0, 16, jq4, ep0, a);
            sts_partials(red, tid, a);
        }
        __syncthreads();
        out_phase(red, H0, bias_s, tid);
        __syncthreads();

        // ---- layer 1 (+ stage x(t+1), consumed only next iter) ----
        if (t + 1 < T_STEPS) {
            for (int idx = tid; idx < ELEMS_BLK * F_IN; idx += NTHREADS) {
                int e = idx / F_IN, f = idx - e * F_IN;
                xs_f[f * ELEMS_BLK + e] =
                    xblk[e * (T_STEPS * F_IN) + (t + 1) * F_IN + f];
            }
        }
        {
            ull a[4][4] = {};
            mv_part(smf + WF_IH1, H0, k0, 16, jq4, ep0, a);
            mv_part(smf + WF_HH1, H1, k0, 16, jq4, ep0, a);
            sts_partials(red, tid, a);
        }
        __syncthreads();
        out_phase(red, H1, bias_s + 64, tid);
        __syncthreads();

        // ---- layer 2 ----
        {
            ull a[4][4] = {};
            mv_part(smf + WF_IH2, H1, k0, 16, jq4, ep0, a);
            mv_part(smf + WF_HH2, H2, k0, 16, jq4, ep0, a);
            sts_partials(red, tid, a);
        }
        __syncthreads();
        out_phase(red, H2, bias_s + 128, tid);
        __syncthreads();
    }

    // ---- FC head on final h2 ([k][16ep] ull == [k][32e] floats) ----
    const float* h2f = (const float*)H2;
    {
        int e  = tid >> 3;
        int mg = tid & 7;
        float contrib = 0.0f;
#pragma unroll
        for (int mi = 0; mi < 4; ++mi) {
            int m = mg * 4 + mi;
            float s = fc1b[m];
#pragma unroll 16
            for (int k = 0; k < HID; ++k)
                s = fmaf(fc1w[m * HID + k], h2f[k * 32 + e], s);
            contrib = fmaf(fc2w[m], fmaxf(s, 0.0f), contrib);
        }
        float* fred = (float*)(smu + U_FCRED);
        fred[tid] = contrib;
    }
    __syncthreads();
    if (tid < ELEMS_BLK) {
        float* fred = (float*)(smu + U_FCRED);
        float s = fc2b[0];
#pragma unroll
        for (int i = 0; i < 8; ++i) s += fred[tid * 8 + i];
        out[blockIdx.x * ELEMS_BLK + tid] = s;
    }
}

extern "C" void kernel_launch(void* const* d_in, const int* in_sizes, int n_in,
                              void* d_out, int out_size)
{
    const float* x    = (const float*)d_in[0];
    const float* Wih0 = (const float*)d_in[1];
    const float* Whh0 = (const float*)d_in[2];
    const float* bih0 = (const float*)d_in[3];
    const float* bhh0 = (const float*)d_in[4];
    const float* Wih1 = (const float*)d_in[5];
    const float* Whh1 = (const float*)d_in[6];
    const float* bih1 = (const float*)d_in[7];
    const float* bhh1 = (const float*)d_in[8];
    const float* Wih2 = (const float*)d_in[9];
    const float* Whh2 = (const float*)d_in[10];
    const float* bih2 = (const float*)d_in[11];
    const float* bhh2 = (const float*)d_in[12];
    const float* fc1w = (const float*)d_in[13];
    const float* fc1b = (const float*)d_in[14];
    const float* fc2w = (const float*)d_in[15];
    const float* fc2b = (const float*)d_in[16];
    float* out = (float*)d_out;

    cudaFuncSetAttribute(rnn_fused_kernel,
                         cudaFuncAttributeMaxDynamicSharedMemorySize, SMEM_BYTES);

    rnn_fused_kernel<<<NBLOCKS, NTHREADS, SMEM_BYTES>>>(
        x, Wih0, Whh0, bih0, bhh0,
        Wih1, Whh1, bih1, bhh1,
        Wih2, Whh2, bih2, bhh2,
        fc1w, fc1b, fc2w, fc2b, out);
}

// round 7
// speedup vs baseline: 1.6501x; 1.0580x over previous
#include <cuda_runtime.h>

// ---------------------------------------------------------------------------
// RNN_32109175505717: 3-layer tanh RNN (B=4096, T=128, HID=64, F=14) + FC head
// R7: 512 threads (4 warps/SMSP), k-split 8, thread tile 4j x 8e.
// Total smem traffic and FFMA2/SMSP identical to R6, but 2x warps to hide
// latency (R6: occ 12.5%, issue 29%, all floors ~2.6x under measured).
// Reduction: 1 shfl.bfly round in-warp, then conflict-free smem red
// (2 partials/slot), uniform all-thread finish. fma floor: 5376 cyc/step.
// ---------------------------------------------------------------------------

#define HID        64
#define F_IN       14
#define T_STEPS    128
#define B_TOTAL    4096
#define ELEMS_BLK  32
#define NTHREADS   512
#define NBLOCKS    (B_TOTAL / ELEMS_BLK)   // 128

typedef unsigned long long ull;

// ---- smem layout ----------------------------------------------------------
// float region (weights transposed to [k][64j]):
#define WF_HH0   0
#define WF_IH1   (WF_HH0 + 64*64)
#define WF_HH1   (WF_IH1 + 64*64)
#define WF_IH2   (WF_HH1 + 64*64)
#define WF_HH2   (WF_IH2 + 64*64)
#define WF_IH0   (WF_HH2 + 64*64)          // 14*64
#define WF_END   (WF_IH0 + 14*64)          // 21376 floats
// ull region:
#define U_BASE   (WF_END / 2)              // 10688 (WF_END even)
#define U_H0     (U_BASE)                  // [64k][16 ep] = 1024 ull
#define U_H1     (U_H0 + 1024)
#define U_H2     (U_H1 + 1024)
#define U_XS     (U_H2 + 1024)             // [14f][16 ep] = 224 ull
#define U_RED    (U_XS + 224)              // [4 q][64 j][16 ep] = 4096 ull
#define U_BIAS   (U_RED + 4096)            // 192 f32 = 96 ull
#define U_FCRED  (U_BIAS + 96)             // 256 f32 = 128 ull
#define SMEM_ULL (U_FCRED + 128)
#define SMEM_BYTES (SMEM_ULL * 8)          // ~146.5 KB

// ---- f32x2 helpers --------------------------------------------------------
__device__ __forceinline__ ull pack2(float lo, float hi) {
    ull r; asm("mov.b64 %0, {%1, %2};" : "=l"(r) : "f"(lo), "f"(hi)); return r;
}
__device__ __forceinline__ void unpack2(ull v, float& lo, float& hi) {
    asm("mov.b64 {%0, %1}, %2;" : "=f"(lo), "=f"(hi) : "l"(v));
}
__device__ __forceinline__ ull fma2(ull a, ull b, ull c) {
    ull d; asm("fma.rn.f32x2 %0, %1, %2, %3;" : "=l"(d) : "l"(a), "l"(b), "l"(c));
    return d;
}
__device__ __forceinline__ ull add2(ull a, ull b) {
    ull d; asm("add.rn.f32x2 %0, %1, %2;" : "=l"(d) : "l"(a), "l"(b));
    return d;
}
__device__ __forceinline__ float fast_tanh(float x) {
    x = fminf(fmaxf(x, -12.0f), 12.0f);
    float e = __expf(x + x);
    return __fdividef(e - 1.0f, e + 1.0f);
}
__device__ __forceinline__ ull tanh2(ull v) {
    float a, b; unpack2(v, a, b);
    return pack2(fast_tanh(a), fast_tanh(b));
}

// ---- matvec partial -------------------------------------------------------
// wf: [k][64j] f32.  hsrc: [k][16 ep] ull.  acc a[4 j][4 ep-ull].
__device__ __forceinline__ void mv_part(const float* __restrict__ wf,
                                        const ull* __restrict__ hsrc,
                                        int koff, int nk, int jq4, int ep0,
                                        ull a[4][4])
{
#pragma unroll 8
    for (int k = 0; k < nk; ++k) {
        const ull* hr = hsrc + (koff + k) * 16 + ep0;
        ulonglong2 h01 = *reinterpret_cast<const ulonglong2*>(hr);
        ulonglong2 h23 = *reinterpret_cast<const ulonglong2*>(hr + 2);
        float4 wv = *reinterpret_cast<const float4*>(wf + (koff + k) * 64 + jq4);
        ull pw0 = pack2(wv.x, wv.x), pw1 = pack2(wv.y, wv.y);
        ull pw2 = pack2(wv.z, wv.z), pw3 = pack2(wv.w, wv.w);
        a[0][0] = fma2(h01.x, pw0, a[0][0]); a[0][1] = fma2(h01.y, pw0, a[0][1]);
        a[0][2] = fma2(h23.x, pw0, a[0][2]); a[0][3] = fma2(h23.y, pw0, a[0][3]);
        a[1][0] = fma2(h01.x, pw1, a[1][0]); a[1][1] = fma2(h01.y, pw1, a[1][1]);
        a[1][2] = fma2(h23.x, pw1, a[1][2]); a[1][3] = fma2(h23.y, pw1, a[1][3]);
        a[2][0] = fma2(h01.x, pw2, a[2][0]); a[2][1] = fma2(h01.y, pw2, a[2][1]);
        a[2][2] = fma2(h23.x, pw2, a[2][2]); a[2][3] = fma2(h23.y, pw2, a[2][3]);
        a[3][0] = fma2(h01.x, pw3, a[3][0]); a[3][1] = fma2(h01.y, pw3, a[3][1]);
        a[3][2] = fma2(h23.x, pw3, a[3][2]); a[3][3] = fma2(h23.y, pw3, a[3][3]);
    }
}

__global__ void __launch_bounds__(NTHREADS, 1)
rnn_fused_kernel(const float* __restrict__ x,
                 const float* __restrict__ Wih0, const float* __restrict__ Whh0,
                 const float* __restrict__ bih0, const float* __restrict__ bhh0,
                 const float* __restrict__ Wih1, const float* __restrict__ Whh1,
                 const float* __restrict__ bih1, const float* __restrict__ bhh1,
                 const float* __restrict__ Wih2, const float* __restrict__ Whh2,
                 const float* __restrict__ bih2, const float* __restrict__ bhh2,
                 const float* __restrict__ fc1w, const float* __restrict__ fc1b,
                 const float* __restrict__ fc2w, const float* __restrict__ fc2b,
                 float* __restrict__ out)
{
    extern __shared__ ull smu[];
    float* smf = (float*)smu;
    const int tid = threadIdx.x;

    // ---- stage weights transposed [k][j] fp32 ----
    {
        const float* gsrc[5] = { Whh0, Wih1, Whh1, Wih2, Whh2 };
        const int    goff[5] = { WF_HH0, WF_IH1, WF_HH1, WF_IH2, WF_HH2 };
#pragma unroll
        for (int m = 0; m < 5; ++m) {
            const float* g = gsrc[m];
            float* s = smf + goff[m];
            for (int idx = tid; idx < 64 * 64; idx += NTHREADS) {
                int j = idx >> 6, k = idx & 63;     // g[j][k]
                s[k * 64 + j] = g[idx];
            }
        }
        for (int idx = tid; idx < 64 * F_IN; idx += NTHREADS) {
            int j = idx / F_IN, f = idx - j * F_IN;
            smf[WF_IH0 + f * 64 + j] = Wih0[idx];
        }
    }
    for (int i = tid; i < 3 * 1024; i += NTHREADS) smu[U_H0 + i] = 0ull;
    float* bias_s = (float*)(smu + U_BIAS);
    if (tid < 64)       bias_s[tid] = bih0[tid] + bhh0[tid];
    else if (tid < 128) bias_s[tid] = bih1[tid - 64] + bhh1[tid - 64];
    else if (tid < 192) bias_s[tid] = bih2[tid - 128] + bhh2[tid - 128];

    // ---- producer mapping ----
    const int w    = tid >> 5;
    const int lane = tid & 31;
    const int kch  = w >> 3;             // 0,1
    const int jqh  = w & 7;              // 0..7
    const int kcl  = lane >> 3;          // 0..3
    const int jql  = (lane >> 2) & 1;
    const int u    = lane & 3;
    const int jq   = jqh * 2 + jql;      // 0..15
    const int jq4  = jq * 4;
    const int ep0  = u * 4;
    const int kc   = kch * 4 + kcl;      // 0..7
    const int k0   = kc * 8;
    const int f0   = kc * 2;
    const int fn   = (F_IN - f0) >= 2 ? 2 : ((F_IN - f0) > 0 ? (F_IN - f0) : 0);
    const int part = kcl >> 1;                   // 0,1
    const bool do_sts = ((kcl & 1) == 0);        // kcl 0 or 2 store partials
    const int q    = part * 2 + kch;             // red quadrant 0..3

    // ---- finisher mapping (all 512 threads) ----
    const int fj  = tid >> 3;            // 0..63 (j)
    const int fep = (tid & 7) * 2;       // ep pair {fep, fep+1}

    const float* xblk = x + (size_t)blockIdx.x * ELEMS_BLK * T_STEPS * F_IN;
    float* xs_f = (float*)(smu + U_XS);
    ull* red = smu + U_RED;
    ull* H[3] = { smu + U_H0, smu + U_H1, smu + U_H2 };

    // stage x(t=0)
    for (int idx = tid; idx < ELEMS_BLK * F_IN; idx += NTHREADS) {
        int e = idx / F_IN, f = idx - e * F_IN;
        xs_f[f * ELEMS_BLK + e] = xblk[e * (T_STEPS * F_IN) + f];
    }
    __syncthreads();

    for (int t = 0; t < T_STEPS; ++t) {
#pragma unroll
        for (int L = 0; L < 3; ++L) {
            // ---------- matvec ----------
            ull a[4][4] = {};
            if (L == 0) {
                if (fn > 0)
                    mv_part(smf + WF_IH0, smu + U_XS, f0, fn, jq4, ep0, a);
                mv_part(smf + WF_HH0, H[0], k0, 8, jq4, ep0, a);
            } else if (L == 1) {
                mv_part(smf + WF_IH1, H[0], k0, 8, jq4, ep0, a);
                mv_part(smf + WF_HH1, H[1], k0, 8, jq4, ep0, a);
            } else {
                mv_part(smf + WF_IH2, H[1], k0, 8, jq4, ep0, a);
                mv_part(smf + WF_HH2, H[2], k0, 8, jq4, ep0, a);
            }

            // ---------- in-warp fold (kcl pairs 0+1, 2+3) ----------
#pragma unroll
            for (int jj = 0; jj < 4; ++jj)
#pragma unroll
                for (int pp = 0; pp < 4; ++pp)
                    a[jj][pp] = add2(a[jj][pp],
                                     __shfl_xor_sync(0xffffffffu, a[jj][pp], 8));

            // ---------- store 2 partials/slot (kcl 0,2 lanes) ----------
            if (do_sts) {
#pragma unroll
                for (int jj = 0; jj < 4; ++jj) {
                    ull* rp = red + ((q * 64) + (jq4 + jj)) * 16 + ep0;
                    *reinterpret_cast<ulonglong2*>(rp) =
                        make_ulonglong2(a[jj][0], a[jj][1]);
                    *reinterpret_cast<ulonglong2*>(rp + 2) =
                        make_ulonglong2(a[jj][2], a[jj][3]);
                }
            }
            __syncthreads();

            // ---------- uniform finish: sum 4 quadrants, tanh, write h ----
            {
                ull s0 = 0ull, s1 = 0ull;
#pragma unroll
                for (int qq = 0; qq < 4; ++qq) {
                    ulonglong2 v = *reinterpret_cast<const ulonglong2*>(
                        red + (qq * 64 + fj) * 16 + fep);
                    s0 = add2(s0, v.x);
                    s1 = add2(s1, v.y);
                }
                float bj = bias_s[L * 64 + fj];
                ull bp = pack2(bj, bj);
                ulonglong2 res;
                res.x = tanh2(add2(s0, bp));
                res.y = tanh2(add2(s1, bp));
                *reinterpret_cast<ulonglong2*>(H[L] + fj * 16 + fep) = res;
            }
            // stage x(t+1) inside layer-0 finish phase (xs readers all pre-bar)
            if (L == 0 && t + 1 < T_STEPS) {
                for (int idx = tid; idx < ELEMS_BLK * F_IN; idx += NTHREADS) {
                    int e = idx / F_IN, f = idx - e * F_IN;
                    xs_f[f * ELEMS_BLK + e] =
                        xblk[e * (T_STEPS * F_IN) + (t + 1) * F_IN + f];
                }
            }
            __syncthreads();
        }
    }

    // ---- FC head on final h2 ([k][16 ep] ull == [k][32 e] floats) ----
    const float* h2f = (const float*)H[2];
    if (tid < 256) {
        int e  = tid >> 3;
        int mg = tid & 7;
        float contrib = 0.0f;
#pragma unroll
        for (int mi = 0; mi < 4; ++mi) {
            int m = mg * 4 + mi;
            float s = fc1b[m];
#pragma unroll 16
            for (int k = 0; k < HID; ++k)
                s = fmaf(fc1w[m * HID + k], h2f[k * 32 + e], s);
            contrib = fmaf(fc2w[m], fmaxf(s, 0.0f), contrib);
        }
        float* fred = (float*)(smu + U_FCRED);
        fred[tid] = contrib;
    }
    __syncthreads();
    if (tid < ELEMS_BLK) {
        float* fred = (float*)(smu + U_FCRED);
        float s = fc2b[0];
#pragma unroll
        for (int i = 0; i < 8; ++i) s += fred[tid * 8 + i];
        out[blockIdx.x * ELEMS_BLK + tid] = s;
    }
}

extern "C" void kernel_launch(void* const* d_in, const int* in_sizes, int n_in,
                              void* d_out, int out_size)
{
    const float* x    = (const float*)d_in[0];
    const float* Wih0 = (const float*)d_in[1];
    const float* Whh0 = (const float*)d_in[2];
    const float* bih0 = (const float*)d_in[3];
    const float* bhh0 = (const float*)d_in[4];
    const float* Wih1 = (const float*)d_in[5];
    const float* Whh1 = (const float*)d_in[6];
    const float* bih1 = (const float*)d_in[7];
    const float* bhh1 = (const float*)d_in[8];
    const float* Wih2 = (const float*)d_in[9];
    const float* Whh2 = (const float*)d_in[10];
    const float* bih2 = (const float*)d_in[11];
    const float* bhh2 = (const float*)d_in[12];
    const float* fc1w = (const float*)d_in[13];
    const float* fc1b = (const float*)d_in[14];
    const float* fc2w = (const float*)d_in[15];
    const float* fc2b = (const float*)d_in[16];
    float* out = (float*)d_out;

    cudaFuncSetAttribute(rnn_fused_kernel,
                         cudaFuncAttributeMaxDynamicSharedMemorySize, SMEM_BYTES);

    rnn_fused_kernel<<<NBLOCKS, NTHREADS, SMEM_BYTES>>>(
        x, Wih0, Whh0, bih0, bhh0,
        Wih1, Whh1, bih1, bhh1,
        Wih2, Whh2, bih2, bhh2,
        fc1w, fc1b, fc2w, fc2b, out);
}